// round 14
// baseline (speedup 1.0000x reference)
#include <cuda_runtime.h>
#include <cuda_bf16.h>
#include <cstdint>

#define LOG2E 1.4426950408889634f
#define SCALE (13.0f / 223.0f)

// ---------------------------------------------------------------------------
// Single fused kernel. Block (56,8) covers one d and 16 consecutive h rows;
// each thread produces 4 consecutive w voxels on TWO rows (ty, ty+8).
//
//  Phase A0 (84 thr): 1x1x1 conv for this block's 2x3x14 small-grid region.
//        One thread per voxel, all 4 classes (unique x loads, W via float4
//        __ldg -> L1). zs[j] = float4 of log2e-scaled logits,
//        j = (dd*3+hh)*14 + iw.
//  Phase A  (224 thr): bilinear (d,h)-lerp -> gs[row][iw] (+ dup at 14).
//  Phase B  (208 thr): per (row, iw0) diff basis b/P/Q -> sb.
//  Main: u=min(t,1), v=t-u; d_i = b_i + u*P_i + v*Q_i; 3x EX2;
//        r = rcp(1+sum); 8x warp-contiguous __stcs STG.128.
// ---------------------------------------------------------------------------
__global__ __launch_bounds__(448, 3) void fused_kernel(const float* __restrict__ x,
                                                       const float* __restrict__ W,
                                                       const float* __restrict__ bias,
                                                       float* __restrict__ out) {
    __shared__ __align__(16) float4 zs[84];        // conv logits (log2 domain)
    __shared__ __align__(16) float4 gs[16][16];    // 15 used (14 + dup)
    __shared__ __align__(16) float4 sb[16][40];    // [row][iw0*3 + {B,P,Q}]

    const int tx = threadIdx.x;   // 0..55
    const int ty = threadIdx.y;   // 0..7
    const int d  = blockIdx.y;
    const int h0 = blockIdx.x * 16;
    const int tid = ty * 56 + tx;

    // block-level source indices
    float pd = (float)d * SCALE;
    int id0 = (int)pd; if (id0 > 12) id0 = 12;
    float wd = pd - (float)id0;
    int ihA = (int)((float)h0 * SCALE);   // <= 12

    // ---- Phase A0: conv for the 84 small voxels this block needs ----
    if (tid < 84) {
        int dd = tid / 42;
        int rem = tid - dd * 42;
        int hh = rem / 14;
        int iw = rem - hh * 14;
        int vd = id0 + dd;                      // <= 13
        int vh = ihA + hh; if (vh > 13) vh = 13;
        int sv = vd * 196 + vh * 14 + iw;

        float acc0 = bias[0], acc1 = bias[1], acc2 = bias[2], acc3 = bias[3];
        const float4* W4 = (const float4*)W;
#pragma unroll
        for (int c4 = 0; c4 < 8; c4++) {
            float4 w0 = __ldg(&W4[c4]);
            float4 w1 = __ldg(&W4[8 + c4]);
            float4 w2 = __ldg(&W4[16 + c4]);
            float4 w3 = __ldg(&W4[24 + c4]);
            float x0 = __ldg(&x[(c4 * 4 + 0) * 2744 + sv]);
            float x1 = __ldg(&x[(c4 * 4 + 1) * 2744 + sv]);
            float x2 = __ldg(&x[(c4 * 4 + 2) * 2744 + sv]);
            float x3 = __ldg(&x[(c4 * 4 + 3) * 2744 + sv]);
            acc0 = fmaf(w0.x, x0, fmaf(w0.y, x1, fmaf(w0.z, x2, fmaf(w0.w, x3, acc0))));
            acc1 = fmaf(w1.x, x0, fmaf(w1.y, x1, fmaf(w1.z, x2, fmaf(w1.w, x3, acc1))));
            acc2 = fmaf(w2.x, x0, fmaf(w2.y, x1, fmaf(w2.z, x2, fmaf(w2.w, x3, acc2))));
            acc3 = fmaf(w3.x, x0, fmaf(w3.y, x1, fmaf(w3.z, x2, fmaf(w3.w, x3, acc3))));
        }
        zs[tid] = make_float4(acc0 * LOG2E, acc1 * LOG2E, acc2 * LOG2E, acc3 * LOG2E);
    }
    __syncthreads();

    // ---- Phase A: fill gs[row][iw], row 0..15, iw 0..13 ----
    if (tid < 224) {
        int row = tid / 14;
        int iw  = tid - row * 14;
        int h   = h0 + row;

        float ph = (float)h * SCALE;
        int ih0 = (int)ph; if (ih0 > 12) ih0 = 12;
        float wh = ph - (float)ih0;
        int dh = ih0 - ihA;              // 0 or 1

        float4 z00 = zs[(dh)     * 14 + iw];
        float4 z01 = zs[(dh + 1) * 14 + iw];
        float4 z10 = zs[(dh + 3) * 14 + iw];
        float4 z11 = zs[(dh + 4) * 14 + iw];
        float4 a0, a1, g;
        a0.x = fmaf(wh, z01.x - z00.x, z00.x);
        a0.y = fmaf(wh, z01.y - z00.y, z00.y);
        a0.z = fmaf(wh, z01.z - z00.z, z00.z);
        a0.w = fmaf(wh, z01.w - z00.w, z00.w);
        a1.x = fmaf(wh, z11.x - z10.x, z10.x);
        a1.y = fmaf(wh, z11.y - z10.y, z10.y);
        a1.z = fmaf(wh, z11.z - z10.z, z10.z);
        a1.w = fmaf(wh, z11.w - z10.w, z10.w);
        g.x = fmaf(wd, a1.x - a0.x, a0.x);
        g.y = fmaf(wd, a1.y - a0.y, a0.y);
        g.z = fmaf(wd, a1.z - a0.z, a0.z);
        g.w = fmaf(wd, a1.w - a0.w, a0.w);
        gs[row][iw] = g;
        if (iw == 13) gs[row][14] = g;   // dup; its segment weight is always 0
    }
    __syncthreads();

    // ---- Phase B: diff basis per (row, iw0), iw0 0..12 ----
    if (tid < 208) {
        int row = tid / 13;
        int iw  = tid - row * 13;
        float4 G0 = gs[row][iw];
        float4 G1 = gs[row][iw + 1];
        float4 G2 = gs[row][iw + 2];
        float D0 = G1.x - G0.x;
        float E0 = G2.x - G1.x;
        sb[row][iw * 3 + 0] = make_float4(G0.y - G0.x, G0.z - G0.x, G0.w - G0.x, 0.f);
        sb[row][iw * 3 + 1] = make_float4((G1.y - G0.y) - D0, (G1.z - G0.z) - D0,
                                          (G1.w - G0.w) - D0, 0.f);
        sb[row][iw * 3 + 2] = make_float4((G2.y - G1.y) - E0, (G2.z - G1.z) - E0,
                                          (G2.w - G1.w) - E0, 0.f);
    }
    __syncthreads();

    // ---- Main: 4 consecutive w on rows ty and ty+8 ----
    const int w0 = tx * 4;
    float pw0 = (float)w0 * SCALE;        // <= 12.83
    int iw0 = (int)pw0;
    float t0 = pw0 - (float)iw0;

    float4 Ba = sb[ty][iw0 * 3 + 0];
    float4 Pa = sb[ty][iw0 * 3 + 1];
    float4 Qa = sb[ty][iw0 * 3 + 2];
    float4 Bb = sb[ty + 8][iw0 * 3 + 0];
    float4 Pb = sb[ty + 8][iw0 * 3 + 1];
    float4 Qb = sb[ty + 8][iw0 * 3 + 2];

    float a0[4], a1[4], a2[4], a3[4];
    float c0[4], c1[4], c2[4], c3[4];

#pragma unroll
    for (int k = 0; k < 4; k++) {
        float t = t0 + (float)k * SCALE;
        float u = fminf(t, 1.0f);
        float v = t - u;

        {   // row a
            float d1 = fmaf(v, Qa.x, fmaf(u, Pa.x, Ba.x));
            float d2 = fmaf(v, Qa.y, fmaf(u, Pa.y, Ba.y));
            float d3 = fmaf(v, Qa.z, fmaf(u, Pa.z, Ba.z));
            float e1 = exp2f(d1);
            float e2 = exp2f(d2);
            float e3 = exp2f(d3);
            float s = 1.0f + ((e1 + e2) + e3);
            float r;
            asm("rcp.approx.f32 %0, %1;" : "=f"(r) : "f"(s));
            a0[k] = r;
            a1[k] = e1 * r;
            a2[k] = e2 * r;
            a3[k] = e3 * r;
        }
        {   // row b
            float d1 = fmaf(v, Qb.x, fmaf(u, Pb.x, Bb.x));
            float d2 = fmaf(v, Qb.y, fmaf(u, Pb.y, Bb.y));
            float d3 = fmaf(v, Qb.z, fmaf(u, Pb.z, Bb.z));
            float e1 = exp2f(d1);
            float e2 = exp2f(d2);
            float e3 = exp2f(d3);
            float s = 1.0f + ((e1 + e2) + e3);
            float r;
            asm("rcp.approx.f32 %0, %1;" : "=f"(r) : "f"(s));
            c0[k] = r;
            c1[k] = e1 * r;
            c2[k] = e2 * r;
            c3[k] = e3 * r;
        }
    }

    const int PLANE4 = (224 * 224 * 224) >> 2;
    const int ROW8_4 = (8 * 224) >> 2;   // 8 h-rows in float4 units
    int idxa = ((d * 224 + h0 + ty) * 224 + w0) >> 2;
    float4* o4 = (float4*)out;

    __stcs(&o4[idxa],                       make_float4(a0[0], a0[1], a0[2], a0[3]));
    __stcs(&o4[idxa + PLANE4],              make_float4(a1[0], a1[1], a1[2], a1[3]));
    __stcs(&o4[idxa + 2 * PLANE4],          make_float4(a2[0], a2[1], a2[2], a2[3]));
    __stcs(&o4[idxa + 3 * PLANE4],          make_float4(a3[0], a3[1], a3[2], a3[3]));
    __stcs(&o4[idxa + ROW8_4],              make_float4(c0[0], c0[1], c0[2], c0[3]));
    __stcs(&o4[idxa + ROW8_4 + PLANE4],     make_float4(c1[0], c1[1], c1[2], c1[3]));
    __stcs(&o4[idxa + ROW8_4 + 2 * PLANE4], make_float4(c2[0], c2[1], c2[2], c2[3]));
    __stcs(&o4[idxa + ROW8_4 + 3 * PLANE4], make_float4(c3[0], c3[1], c3[2], c3[3]));
}

extern "C" void kernel_launch(void* const* d_in, const int* in_sizes, int n_in,
                              void* d_out, int out_size) {
    const float* x = (const float*)d_in[0];  // [1,32,14,14,14]
    const float* W = (const float*)d_in[1];  // [4,32]
    const float* b = (const float*)d_in[2];  // [4]
    float* out = (float*)d_out;              // [1,4,224,224,224]

    dim3 block(56, 8);
    dim3 grid(14, 224);  // (h-group of 16, d)
    fused_kernel<<<grid, block>>>(x, W, b, out);
}

// round 15
// speedup vs baseline: 1.5758x; 1.5758x over previous
#include <cuda_runtime.h>
#include <cuda_bf16.h>
#include <cstdint>

// channel-interleaved logits on the 14^3 grid, pre-scaled by log2(e):
// g_z4[v*4 + c]  (43 KB)
__device__ float g_z4[2744 * 4];

#define LOG2E 1.4426950408889634f
#define SCALE (13.0f / 223.0f)

// ---------------------------------------------------------------------------
// Kernel 1: 1x1x1 conv on the small grid -> interleaved float4 logits.
// One thread per (class, voxel). Triggers PDL completion at entry.
// ---------------------------------------------------------------------------
__global__ void conv_small_kernel(const float* __restrict__ x,
                                  const float* __restrict__ W,
                                  const float* __restrict__ b) {
#if __CUDA_ARCH__ >= 900
    cudaTriggerProgrammaticLaunchCompletion();
#endif
    int idx = blockIdx.x * blockDim.x + threadIdx.x;
    if (idx >= 4 * 2744) return;
    int v = idx >> 2;
    int o = idx & 3;
    float acc = b[o];
    const float* wrow = W + o * 32;
#pragma unroll
    for (int c = 0; c < 32; c++) {
        acc = fmaf(wrow[c], x[c * 2744 + v], acc);
    }
    g_z4[idx] = acc * LOG2E;   // coalesced interleaved write
}

// ---------------------------------------------------------------------------
// Kernel 2 (R12 verified best): block (56,8) covers one d and 16 consecutive
// h rows; each thread produces 4 consecutive w voxels on TWO rows (ty, ty+8).
//  Phase A (224 thr): bilinear (d,h)-lerp -> gs[row][iw] (+ dup at 14).
//  Phase B (208 thr): per (row, iw0) diff basis b/P/Q -> sb (computed once,
//          shared by the ~4.3 threads per row with the same iw0).
//  Main: u=min(t,1), v=t-u; d_i = b_i + u*P_i + v*Q_i; 3x MUFU.EX2;
//        r = rcp.approx(1+sum); p0=r, p_i=e_i*r.
//  Stores: 8x warp-contiguous __stcs (st.global.cs.128, evict-first —
//        output is write-once, keep it from thrashing L2 in the replay loop).
// ---------------------------------------------------------------------------
__global__ __launch_bounds__(448) void upsample_softmax_kernel(float* __restrict__ out) {
    __shared__ __align__(16) float4 gs[16][16];    // 15 used (14 + dup)
    __shared__ __align__(16) float4 sb[16][40];    // [row][iw0*3 + {B,P,Q}]

#if __CUDA_ARCH__ >= 900
    cudaGridDependencySynchronize();
#endif

    const int tx = threadIdx.x;   // 0..55
    const int ty = threadIdx.y;   // 0..7
    const int d  = blockIdx.y;
    const int h0 = blockIdx.x * 16;
    const int tid = ty * 56 + tx;

    // ---- Phase A: fill gs[row][iw], row 0..15, iw 0..13 ----
    if (tid < 224) {
        int row = tid / 14;
        int iw  = tid - row * 14;
        int h   = h0 + row;

        float pd = (float)d * SCALE;
        int id0 = (int)pd; if (id0 > 12) id0 = 12;
        float wd = pd - (float)id0;
        float ph = (float)h * SCALE;
        int ih0 = (int)ph; if (ih0 > 12) ih0 = 12;
        float wh = ph - (float)ih0;

        const float4* z4 = (const float4*)g_z4;
        int base = (id0 * 14 + ih0) * 14 + iw;
        float4 z00 = z4[base];
        float4 z01 = z4[base + 14];
        float4 z10 = z4[base + 196];
        float4 z11 = z4[base + 210];
        float4 a0, a1, g;
        a0.x = fmaf(wh, z01.x - z00.x, z00.x);
        a0.y = fmaf(wh, z01.y - z00.y, z00.y);
        a0.z = fmaf(wh, z01.z - z00.z, z00.z);
        a0.w = fmaf(wh, z01.w - z00.w, z00.w);
        a1.x = fmaf(wh, z11.x - z10.x, z10.x);
        a1.y = fmaf(wh, z11.y - z10.y, z10.y);
        a1.z = fmaf(wh, z11.z - z10.z, z10.z);
        a1.w = fmaf(wh, z11.w - z10.w, z10.w);
        g.x = fmaf(wd, a1.x - a0.x, a0.x);
        g.y = fmaf(wd, a1.y - a0.y, a0.y);
        g.z = fmaf(wd, a1.z - a0.z, a0.z);
        g.w = fmaf(wd, a1.w - a0.w, a0.w);
        gs[row][iw] = g;
        if (iw == 13) gs[row][14] = g;   // dup; its segment weight is always 0
    }
    __syncthreads();

    // ---- Phase B: diff basis per (row, iw0), iw0 0..12 ----
    if (tid < 208) {
        int row = tid / 13;
        int iw  = tid - row * 13;
        float4 G0 = gs[row][iw];
        float4 G1 = gs[row][iw + 1];
        float4 G2 = gs[row][iw + 2];
        float D0 = G1.x - G0.x;
        float E0 = G2.x - G1.x;
        sb[row][iw * 3 + 0] = make_float4(G0.y - G0.x, G0.z - G0.x, G0.w - G0.x, 0.f);
        sb[row][iw * 3 + 1] = make_float4((G1.y - G0.y) - D0, (G1.z - G0.z) - D0,
                                          (G1.w - G0.w) - D0, 0.f);
        sb[row][iw * 3 + 2] = make_float4((G2.y - G1.y) - E0, (G2.z - G1.z) - E0,
                                          (G2.w - G1.w) - E0, 0.f);
    }
    __syncthreads();

    // ---- Main: 4 consecutive w on rows ty and ty+8 ----
    const int w0 = tx * 4;
    float pw0 = (float)w0 * SCALE;        // <= 12.83
    int iw0 = (int)pw0;
    float t0 = pw0 - (float)iw0;

    float4 Ba = sb[ty][iw0 * 3 + 0];
    float4 Pa = sb[ty][iw0 * 3 + 1];
    float4 Qa = sb[ty][iw0 * 3 + 2];
    float4 Bb = sb[ty + 8][iw0 * 3 + 0];
    float4 Pb = sb[ty + 8][iw0 * 3 + 1];
    float4 Qb = sb[ty + 8][iw0 * 3 + 2];

    float a0[4], a1[4], a2[4], a3[4];
    float c0[4], c1[4], c2[4], c3[4];

#pragma unroll
    for (int k = 0; k < 4; k++) {
        float t = t0 + (float)k * SCALE;
        float u = fminf(t, 1.0f);
        float v = t - u;

        {   // row a
            float d1 = fmaf(v, Qa.x, fmaf(u, Pa.x, Ba.x));
            float d2 = fmaf(v, Qa.y, fmaf(u, Pa.y, Ba.y));
            float d3 = fmaf(v, Qa.z, fmaf(u, Pa.z, Ba.z));
            float e1 = exp2f(d1);
            float e2 = exp2f(d2);
            float e3 = exp2f(d3);
            float s = 1.0f + ((e1 + e2) + e3);
            float r;
            asm("rcp.approx.f32 %0, %1;" : "=f"(r) : "f"(s));
            a0[k] = r;
            a1[k] = e1 * r;
            a2[k] = e2 * r;
            a3[k] = e3 * r;
        }
        {   // row b
            float d1 = fmaf(v, Qb.x, fmaf(u, Pb.x, Bb.x));
            float d2 = fmaf(v, Qb.y, fmaf(u, Pb.y, Bb.y));
            float d3 = fmaf(v, Qb.z, fmaf(u, Pb.z, Bb.z));
            float e1 = exp2f(d1);
            float e2 = exp2f(d2);
            float e3 = exp2f(d3);
            float s = 1.0f + ((e1 + e2) + e3);
            float r;
            asm("rcp.approx.f32 %0, %1;" : "=f"(r) : "f"(s));
            c0[k] = r;
            c1[k] = e1 * r;
            c2[k] = e2 * r;
            c3[k] = e3 * r;
        }
    }

    const int PLANE4 = (224 * 224 * 224) >> 2;
    const int ROW8_4 = (8 * 224) >> 2;   // 8 h-rows in float4 units
    int idxa = ((d * 224 + h0 + ty) * 224 + w0) >> 2;
    float4* o4 = (float4*)out;

    __stcs(&o4[idxa],                       make_float4(a0[0], a0[1], a0[2], a0[3]));
    __stcs(&o4[idxa + PLANE4],              make_float4(a1[0], a1[1], a1[2], a1[3]));
    __stcs(&o4[idxa + 2 * PLANE4],          make_float4(a2[0], a2[1], a2[2], a2[3]));
    __stcs(&o4[idxa + 3 * PLANE4],          make_float4(a3[0], a3[1], a3[2], a3[3]));
    __stcs(&o4[idxa + ROW8_4],              make_float4(c0[0], c0[1], c0[2], c0[3]));
    __stcs(&o4[idxa + ROW8_4 + PLANE4],     make_float4(c1[0], c1[1], c1[2], c1[3]));
    __stcs(&o4[idxa + ROW8_4 + 2 * PLANE4], make_float4(c2[0], c2[1], c2[2], c2[3]));
    __stcs(&o4[idxa + ROW8_4 + 3 * PLANE4], make_float4(c3[0], c3[1], c3[2], c3[3]));
}

extern "C" void kernel_launch(void* const* d_in, const int* in_sizes, int n_in,
                              void* d_out, int out_size) {
    const float* x = (const float*)d_in[0];  // [1,32,14,14,14]
    const float* W = (const float*)d_in[1];  // [4,32]
    const float* b = (const float*)d_in[2];  // [4]
    float* out = (float*)d_out;              // [1,4,224,224,224]

    conv_small_kernel<<<(4 * 2744 + 255) / 256, 256>>>(x, W, b);

    // PDL launch of the big kernel: overlaps its launch with k1's execution;
    // cudaGridDependencySynchronize() in-kernel enforces the data dependency.
    dim3 block(56, 8);
    dim3 grid(14, 224);  // (h-group of 16, d)

    cudaLaunchConfig_t cfg = {};
    cfg.gridDim = grid;
    cfg.blockDim = block;
    cfg.dynamicSmemBytes = 0;
    cfg.stream = 0;
    cudaLaunchAttribute attrs[1];
    attrs[0].id = cudaLaunchAttributeProgrammaticStreamSerialization;
    attrs[0].val.programmaticStreamSerializationAllowed = 1;
    cfg.attrs = attrs;
    cfg.numAttrs = 1;
    cudaLaunchKernelEx(&cfg, upsample_softmax_kernel, out);
}